// round 17
// baseline (speedup 1.0000x reference)
#include <cuda_runtime.h>
#include <math.h>
#include <stdint.h>

#define B 4
#define T 64
#define F 64
#define U 64
#define M 64
#define TF (T*F)
#define NTH 1024

// Accurate tanh for value paths (h, ms): abs err ~1e-7.
__device__ __forceinline__ float fast_tanh(float x) {
    float e = __expf(2.0f * x);
    return 1.0f - __fdividef(2.0f, e + 1.0f);
}
// Single-MUFU f32 tanh for the argmax-only score path (proven argmax-safe).
__device__ __forceinline__ float tanh_mufu(float x) {
    float y; asm("tanh.approx.f32 %0, %1;" : "=f"(y) : "f"(x)); return y;
}
__device__ __forceinline__ uint32_t smem_u32(const void* p) {
    uint32_t a;
    asm("{ .reg .u64 t; cvta.to.shared.u64 t, %1; cvt.u32.u64 %0, t; }" : "=r"(a) : "l"(p));
    return a;
}
__device__ __forceinline__ void stc_f32(uint32_t saddr, int rank, float v) {
    uint32_t rr;
    asm volatile("mapa.shared::cluster.u32 %0, %1, %2;" : "=r"(rr) : "r"(saddr), "r"(rank));
    asm volatile("st.shared::cluster.f32 [%0], %1;" :: "r"(rr), "f"(v) : "memory");
}
__device__ __forceinline__ void stc_s32(uint32_t saddr, int rank, int v) {
    uint32_t rr;
    asm volatile("mapa.shared::cluster.u32 %0, %1, %2;" : "=r"(rr) : "r"(saddr), "r"(rank));
    asm volatile("st.shared::cluster.u32 [%0], %1;" :: "r"(rr), "r"(v) : "memory");
}
__device__ __forceinline__ void stc_u64(uint32_t saddr, int rank, unsigned long long v) {
    uint32_t rr;
    asm volatile("mapa.shared::cluster.u32 %0, %1, %2;" : "=r"(rr) : "r"(saddr), "r"(rank));
    asm volatile("st.shared::cluster.u64 [%0], %1;" :: "r"(rr), "l"(v) : "memory");
}
__device__ __forceinline__ void cluster_arrive() {
    asm volatile("barrier.cluster.arrive.aligned;" ::: "memory");
}
__device__ __forceinline__ void cluster_wait() {
    asm volatile("barrier.cluster.wait.aligned;" ::: "memory");
}

// =====================================================================
// CPB=16 kernel: 4 rows/CTA, 32 warps. Weights read ONCE per CTA.
// Candidate exchange scattered to f-owner ranks (512B) + tiny wmm
// broadcast; 3 cluster barriers total (A1, A2, B).
// =====================================================================
__global__ void __launch_bounds__(NTH)
fused16(const float* __restrict__ inp,
        const float* __restrict__ Wk,
        const float* __restrict__ bk,
        const float* __restrict__ Wv,
        const float* __restrict__ bv,
        const float* __restrict__ w_s,
        const float* __restrict__ mem_keys,
        const float* __restrict__ mem_vals,
        float* __restrict__ d_out) {
    constexpr int CPB = 16, RPC = 4;
    const int b    = blockIdx.x / CPB;
    const int r    = blockIdx.x % CPB;
    const int tid  = threadIdx.x;
    const int w    = tid >> 5;
    const int lane = tid & 31;

    __shared__ __align__(16) float s_U[4096];      // 16KB union scratch
    __shared__ __align__(16) float s_in[RPC][F];
    __shared__ float s_h [RPC][U];
    __shared__ float s_o [RPC][F];
    __shared__ unsigned long long s_candloc[F];
    __shared__ unsigned long long s_candrecv[CPB][4];  // [src rank][slot]
    __shared__ unsigned long long s_wpair[CPB];
    __shared__ int   s_idxt[T];
    __shared__ float s_lp[CPB][M];
    __shared__ float s_ws[F];
    __shared__ float s_attn[M];
    __shared__ float s_amax[RPC], s_amin[RPC];
    __shared__ float s_wmm[2];
    __shared__ float s_imp;

    if (tid < F) s_ws[tid] = w_s[tid];
    const float wlast = __ldg(w_s + 63);

    // ---- stage inputs: 256 floats ----
    if (tid < RPC*F)
        s_in[tid >> 6][tid & 63] = inp[(b*T + r*RPC)*F + tid];
    __syncthreads();

    // ---- h partials: warp (uh = w>>4, fc = w&15); Wk read once ----
    {
        const int fc = w & 15, uh = w >> 4;
        const int u = uh*32 + lane;
        float a[RPC] = {0.f, 0.f, 0.f, 0.f};
        #pragma unroll
        for (int f = 0; f < 4; ++f) {
            float kk = Wk[(fc*4 + f)*U + u];
            #pragma unroll
            for (int q = 0; q < RPC; ++q)
                a[q] = fmaf(s_in[q][fc*4 + f], kk, a[q]);
        }
        #pragma unroll
        for (int q = 0; q < RPC; ++q)
            s_U[(fc*RPC + q)*U + u] = a[q];
    }
    __syncthreads();
    if (tid < RPC*U) {
        const int t = tid >> 6, u = tid & 63;
        float s = __ldg(bk + u);
        #pragma unroll
        for (int c = 0; c < 16; ++c) s += s_U[(c*RPC + t)*U + u];
        s_h[t][u] = fast_tanh(s);
    }
    __syncthreads();

    // ---- output partials: warp (fh = w>>4, uc = w&15); Wv read once ----
    {
        const int uc = w & 15, fh = w >> 4;
        const int f = fh*32 + lane;
        float o[RPC] = {0.f, 0.f, 0.f, 0.f};
        #pragma unroll
        for (int u = 0; u < 4; ++u) {
            float vv = Wv[(uc*4 + u)*F + f];
            #pragma unroll
            for (int q = 0; q < RPC; ++q)
                o[q] = fmaf(s_h[q][uc*4 + u], vv, o[q]);
        }
        #pragma unroll
        for (int q = 0; q < RPC; ++q)
            s_U[(uc*RPC + q)*F + f] = o[q];
    }
    __syncthreads();
    if (tid < RPC*F) {
        const int t = tid >> 6, f = tid & 63;
        float o = __ldg(bv + f);
        #pragma unroll
        for (int c = 0; c < 16; ++c) o += s_U[(c*RPC + t)*F + f];
        s_o[t][f] = o;
        d_out[2*B*T + (b*T + r*RPC)*F + tid] = o;
    }
    __syncthreads();

    // ---- score partials: 8 warps/row, 8 u each; f0 = 2*lane ----
    {
        const int tl = w >> 3, sub = w & 7;
        const int ubase = sub*8;
        const int f0 = 2*lane;
        const float c0 = s_o[tl][f0] * wlast, c1 = s_o[tl][f0+1] * wlast;
        float sc0 = 0.f, sc1 = 0.f;
        #pragma unroll
        for (int u = 0; u < 8; ++u) {
            float hv = s_h[tl][ubase + u];
            sc0 += tanh_mufu(hv * c0);
            sc1 += tanh_mufu(hv * c1);
        }
        s_U[(sub*RPC + tl)*F + f0]     = sc0;
        s_U[(sub*RPC + tl)*F + f0 + 1] = sc1;
    }
    __syncthreads();

    // ---- idx_t (warps 0..3): partial-sum + argmax_f (first max) ----
    if (w < RPC) {
        const int f0 = 2*lane;
        float sc0 = 0.f, sc1 = 0.f;
        #pragma unroll
        for (int q = 0; q < 8; ++q) {
            sc0 += s_U[(q*RPC + w)*F + f0];
            sc1 += s_U[(q*RPC + w)*F + f0 + 1];
        }
        float bvv = sc0; int bf = f0;
        if (sc1 > bvv) { bvv = sc1; bf = f0 + 1; }
        #pragma unroll
        for (int o = 16; o; o >>= 1) {
            float ov = __shfl_xor_sync(0xffffffffu, bvv, o);
            int   of = __shfl_xor_sync(0xffffffffu, bf,  o);
            if (ov > bvv || (ov == bvv && of < bf)) { bvv = ov; bf = of; }
        }
        if (lane < CPB)
            stc_s32(smem_u32(&s_idxt[r*RPC + w]), lane, bf);
    }
    // ---- per-f column-max candidate (warps 4,5), same sum order ----
    else if (w < RPC + 2) {
        const int f = (w - RPC)*32 + lane;
        float best = -INFINITY; int bt = 0;
        #pragma unroll
        for (int t = 0; t < RPC; ++t) {
            float v = 0.f;
            #pragma unroll
            for (int q = 0; q < 8; ++q) v += s_U[(q*RPC + t)*F + f];
            if (v > best) { best = v; bt = t; }
        }
        s_candloc[f] =
            ((unsigned long long)__float_as_uint(best) << 32) | (unsigned)(r*RPC + bt);
    }
    __syncthreads();

    // ---- scatter candidates to f-owner rank (f>>2); 64 pushes ----
    if (tid < F)
        stc_u64(smem_u32(&s_candrecv[r][tid & 3]), tid >> 2, s_candloc[tid]);
    cluster_arrive();
    cluster_wait();   // A1: idx_t + owner candidates delivered

    // ---- owner (warp 0, lanes 0..3): global idx_f for its 4 f's ----
    if (w == 0) {
        float wv = -INFINITY, wn = INFINITY;
        if (lane < 4) {
            float best = -INFINITY; int bt = 0;
            #pragma unroll
            for (int rr = 0; rr < CPB; ++rr) {     // ascending rank = ascending t
                unsigned long long c = s_candrecv[rr][lane];
                float v = __uint_as_float((unsigned)(c >> 32));
                if (v > best) { best = v; bt = (int)(c & 0xffffffffu); }
            }
            wv = s_ws[bt];
            wn = wv;
        }
        #pragma unroll
        for (int o = 16; o; o >>= 1) {
            wv = fmaxf(wv, __shfl_xor_sync(0xffffffffu, wv, o));
            wn = fminf(wn, __shfl_xor_sync(0xffffffffu, wn, o));
        }
        // broadcast packed (wmax,wmin) of OUR 4 f's to every rank
        if (lane < CPB) {
            unsigned long long pk =
                ((unsigned long long)__float_as_uint(wv) << 32) | __float_as_uint(wn);
            stc_u64(smem_u32(&s_wpair[r]), lane, pk);
        }
    }
    // ---- amax/amin: warps 16..19, row = w-16 (needs idx_t, post-A1) ----
    else if (w >= 16 && w < 16 + RPC) {
        const int t = w - 16;
        float v0 = s_h[t][s_idxt[lane]];
        float v1 = s_h[t][s_idxt[lane + 32]];
        float mx = fmaxf(v0, v1), mn = fminf(v0, v1);
        #pragma unroll
        for (int o = 16; o; o >>= 1) {
            mx = fmaxf(mx, __shfl_xor_sync(0xffffffffu, mx, o));
            mn = fminf(mn, __shfl_xor_sync(0xffffffffu, mn, o));
        }
        if (lane == 0) { s_amax[t] = mx; s_amin[t] = mn; }
    }
    __syncthreads();
    cluster_arrive();
    cluster_wait();   // A2: all 16 wmm pairs delivered

    if (w == 0) {     // combine 16 (wmax,wmin) pairs
        float mx = -INFINITY, mn = INFINITY;
        if (lane < CPB) {
            unsigned long long pk = s_wpair[lane];
            mx = __uint_as_float((unsigned)(pk >> 32));
            mn = __uint_as_float((unsigned)(pk & 0xffffffffu));
        }
        #pragma unroll
        for (int o = 16; o; o >>= 1) {
            mx = fmaxf(mx, __shfl_xor_sync(0xffffffffu, mx, o));
            mn = fminf(mn, __shfl_xor_sync(0xffffffffu, mn, o));
        }
        if (lane == 0) { s_wmm[0] = mx; s_wmm[1] = mn; }
    }
    __syncthreads();

    // ---- ms (256 elems) ----
    if (tid < RPC*F) {
        const int t = tid >> 6;
        const float c   = s_o[t][tid & 63];
        const float wmax = s_wmm[0], wmin = s_wmm[1];
        const float amx = s_amax[t], amn = s_amin[t];
        float m = fmaxf(fmaxf(amx*wmax*c, amx*wmin*c),
                        fmaxf(amn*wmax*c, amn*wmin*c));
        s_U[tid] = fast_tanh(m);
    }
    __syncthreads();

    // ---- logit partials: 32 warps, 2 m each over 256-elem slice ----
    {
        const float4* __restrict__ ms4 = (const float4*)s_U;
        #pragma unroll
        for (int k = 0; k < 2; ++k) {
            const int m = w*2 + k;
            const float4* __restrict__ key4 =
                (const float4*)(mem_keys + m*TF + r*(RPC*F));
            float p0 = 0.f, p1 = 0.f, p2 = 0.f, p3 = 0.f;
            #pragma unroll
            for (int c = 0; c < 2; ++c) {
                float4 kk = key4[c*32 + lane];
                float4 mm = ms4[c*32 + lane];
                p0 = fmaf(kk.x, mm.x, p0);
                p1 = fmaf(kk.y, mm.y, p1);
                p2 = fmaf(kk.z, mm.z, p2);
                p3 = fmaf(kk.w, mm.w, p3);
            }
            float acc = (p0 + p1) + (p2 + p3);
            #pragma unroll
            for (int o = 16; o; o >>= 1)
                acc += __shfl_xor_sync(0xffffffffu, acc, o);
            if (lane < CPB)
                stc_f32(smem_u32(&s_lp[r][m]), lane, acc);
        }
    }
    cluster_arrive();

    // ---- window B: prefetch mem_vals rows this thread needs ----
    float rv[4];
    {
        const int f = tid & 63, q = tid >> 6;
        #pragma unroll
        for (int k = 0; k < 4; ++k)
            rv[k] = __ldg(mem_vals + (q*4 + k)*F + f);
    }
    cluster_wait();   // B: all logit partials delivered

    // ---- softmax / importance (single warp) ----
    if (w == 0) {
        float l0 = 0.f, l1 = 0.f;
        #pragma unroll
        for (int rr = 0; rr < CPB; ++rr) {
            l0 += s_lp[rr][lane];
            l1 += s_lp[rr][lane + 32];
        }
        float mx = fmaxf(l0, l1);
        #pragma unroll
        for (int o = 16; o; o >>= 1)
            mx = fmaxf(mx, __shfl_xor_sync(0xffffffffu, mx, o));
        float e0 = __expf(l0 - mx), e1 = __expf(l1 - mx);
        float s = e0 + e1;
        #pragma unroll
        for (int o = 16; o; o >>= 1)
            s += __shfl_xor_sync(0xffffffffu, s, o);
        float inv = 1.0f / s;
        s_attn[lane]      = e0 * inv;
        s_attn[lane + 32] = e1 * inv;
        if (lane == 0) s_imp = inv;   // max(attn) = exp(0)/sum
    }
    __syncthreads();

    // ---- targets partials: 16 groups x 4 m, into s_U[2048..3072) ----
    {
        const int f = tid & 63, q = tid >> 6;
        float acc = 0.f;
        #pragma unroll
        for (int k = 0; k < 4; ++k)
            acc = fmaf(s_attn[q*4 + k], rv[k], acc);
        s_U[2048 + q*64 + f] = acc;
    }
    __syncthreads();

    // ---- dist + importances: warps 0..3, row = w ----
    if (w < RPC) {
        float tg0 = 0.f, tg1 = 0.f;
        #pragma unroll
        for (int q = 0; q < 16; ++q) {
            tg0 += s_U[2048 + q*64 + lane];
            tg1 += s_U[2048 + q*64 + lane + 32];
        }
        float d0 = s_in[w][lane]      - tg0;
        float d1 = s_in[w][lane + 32] - tg1;
        float a2 = d0*d0 + d1*d1;
        #pragma unroll
        for (int o = 16; o; o >>= 1)
            a2 += __shfl_xor_sync(0xffffffffu, a2, o);
        if (lane == 0) {
            float nrm = sqrtf(a2);
            float hs  = fminf(fmaxf(0.2f*nrm + 0.5f, 0.f), 1.f);
            d_out[b*T + r*RPC + w]       = 0.5f - hs;
            d_out[B*T + b*T + r*RPC + w] = s_imp;
        }
    }
}

// =====================================================================
// Fallback: proven R16 kernel (CPB=8).
// =====================================================================
__global__ void __launch_bounds__(NTH)
fused8(const float* __restrict__ inp,
       const float* __restrict__ Wk,
       const float* __restrict__ bk,
       const float* __restrict__ Wv,
       const float* __restrict__ bv,
       const float* __restrict__ w_s,
       const float* __restrict__ mem_keys,
       const float* __restrict__ mem_vals,
       float* __restrict__ d_out) {
    constexpr int CPB = 8, RPC = 8;
    const int b    = blockIdx.x / CPB;
    const int r    = blockIdx.x % CPB;
    const int tid  = threadIdx.x;
    const int w    = tid >> 5;
    const int lane = tid & 31;

    __shared__ __align__(16) float s_U[16*RPC*U];
    __shared__ __align__(16) float s_in[RPC][F];
    __shared__ float s_h [RPC][U];
    __shared__ float s_o [RPC][F];
    __shared__ unsigned long long s_candloc[F];
    __shared__ unsigned long long s_cand[CPB][F];
    __shared__ int   s_idxt[T];
    __shared__ float s_lp[CPB][M];
    __shared__ float s_ws[F];
    __shared__ float s_attn[M];
    __shared__ float s_amax[RPC], s_amin[RPC];
    __shared__ float s_wmm[2];
    __shared__ float s_imp;

    if (tid < F) s_ws[tid] = w_s[tid];
    const float wlast = __ldg(w_s + 63);

    if (tid < RPC*F)
        s_in[tid >> 6][tid & 63] = inp[(b*T + r*RPC)*F + tid];
    __syncthreads();

    {
        const int tg = w >> 4, fc = w & 15;
        const int u0 = 2*lane;
        float a0[4] = {0,0,0,0}, a1[4] = {0,0,0,0};
        #pragma unroll
        for (int f = 0; f < 4; ++f) {
            float2 kk = *(const float2*)(Wk + (fc*4 + f)*U + u0);
            #pragma unroll
            for (int q = 0; q < 4; ++q) {
                float x = s_in[tg*4 + q][fc*4 + f];
                a0[q] = fmaf(x, kk.x, a0[q]);
                a1[q] = fmaf(x, kk.y, a1[q]);
            }
        }
        #pragma unroll
        for (int q = 0; q < 4; ++q) {
            s_U[(fc*RPC + tg*4 + q)*U + u0]     = a0[q];
            s_U[(fc*RPC + tg*4 + q)*U + u0 + 1] = a1[q];
        }
    }
    __syncthreads();
    if (tid < RPC*U) {
        const int t = tid >> 6, u = tid & 63;
        float s = __ldg(bk + u);
        #pragma unroll
        for (int c = 0; c < 16; ++c) s += s_U[(c*RPC + t)*U + u];
        s_h[t][u] = fast_tanh(s);
    }
    __syncthreads();

    {
        const int tg = w >> 4, uc = w & 15;
        const int f0 = 2*lane;
        float o0[4] = {0,0,0,0}, o1[4] = {0,0,0,0};
        #pragma unroll
        for (int u = 0; u < 4; ++u) {
            float2 vv = *(const float2*)(Wv + (uc*4 + u)*F + f0);
            #pragma unroll
            for (int q = 0; q < 4; ++q) {
                float hv = s_h[tg*4 + q][uc*4 + u];
                o0[q] = fmaf(hv, vv.x, o0[q]);
                o1[q] = fmaf(hv, vv.y, o1[q]);
            }
        }
        #pragma unroll
        for (int q = 0; q < 4; ++q) {
            s_U[(uc*RPC + tg*4 + q)*F + f0]     = o0[q];
            s_U[(uc*RPC + tg*4 + q)*F + f0 + 1] = o1[q];
        }
    }
    __syncthreads();
    if (tid < RPC*F) {
        const int t = tid >> 6, f = tid & 63;
        float o = __ldg(bv + f);
        #pragma unroll
        for (int c = 0; c < 16; ++c) o += s_U[(c*RPC + t)*F + f];
        s_o[t][f] = o;
        d_out[2*B*T + (b*T + r*RPC)*F + tid] = o;
    }
    __syncthreads();

    {
        const int tl = w >> 2, sub = w & 3;
        const int ubase = sub*16;
        const int f0 = 2*lane;
        const float c0 = s_o[tl][f0] * wlast, c1 = s_o[tl][f0+1] * wlast;
        float sc0 = 0.f, sc1 = 0.f;
        #pragma unroll
        for (int u = 0; u < 16; ++u) {
            float hv = s_h[tl][ubase + u];
            sc0 += tanh_mufu(hv * c0);
            sc1 += tanh_mufu(hv * c1);
        }
        s_U[(sub*RPC + tl)*F + f0]     = sc0;
        s_U[(sub*RPC + tl)*F + f0 + 1] = sc1;
    }
    __syncthreads();

    if (w < RPC) {
        const int f0 = 2*lane;
        float sc0 = 0.f, sc1 = 0.f;
        #pragma unroll
        for (int q = 0; q < 4; ++q) {
            sc0 += s_U[(q*RPC + w)*F + f0];
            sc1 += s_U[(q*RPC + w)*F + f0 + 1];
        }
        float bvv = sc0; int bf = f0;
        if (sc1 > bvv) { bvv = sc1; bf = f0 + 1; }
        #pragma unroll
        for (int o = 16; o; o >>= 1) {
            float ov = __shfl_xor_sync(0xffffffffu, bvv, o);
            int   of = __shfl_xor_sync(0xffffffffu, bf,  o);
            if (ov > bvv || (ov == bvv && of < bf)) { bvv = ov; bf = of; }
        }
        if (lane < CPB)
            stc_s32(smem_u32(&s_idxt[r*RPC + w]), lane, bf);
    } else if (w < RPC + 2) {
        const int f = (w - RPC)*32 + lane;
        float best = -INFINITY; int bt = 0;
        #pragma unroll
        for (int t = 0; t < RPC; ++t) {
            float v = 0.f;
            #pragma unroll
            for (int q = 0; q < 4; ++q) v += s_U[(q*RPC + t)*F + f];
            if (v > best) { best = v; bt = t; }
        }
        s_candloc[f] =
            ((unsigned long long)__float_as_uint(best) << 32) | (unsigned)(r*RPC + bt);
    }
    __syncthreads();

    if (tid < F*CPB)
        stc_u64(smem_u32(&s_cand[r][tid & 63]), tid >> 6, s_candloc[tid & 63]);
    cluster_arrive();
    cluster_wait();

    if (w == 0) {
        float wv[2];
        #pragma unroll
        for (int hh = 0; hh < 2; ++hh) {
            const int f = lane + hh*32;
            unsigned long long c = s_cand[0][f];
            float best = __uint_as_float((unsigned)(c >> 32));
            int   bt   = (int)(c & 0xffffffffu);
            #pragma unroll
            for (int rr = 1; rr < CPB; ++rr) {
                unsigned long long cc = s_cand[rr][f];
                float v = __uint_as_float((unsigned)(cc >> 32));
                if (v > best) { best = v; bt = (int)(cc & 0xffffffffu); }
            }
            wv[hh] = s_ws[bt];
        }
        float mx = fmaxf(wv[0], wv[1]), mn = fminf(wv[0], wv[1]);
        #pragma unroll
        for (int o = 16; o; o >>= 1) {
            mx = fmaxf(mx, __shfl_xor_sync(0xffffffffu, mx, o));
            mn = fminf(mn, __shfl_xor_sync(0xffffffffu, mn, o));
        }
        if (lane == 0) { s_wmm[0] = mx; s_wmm[1] = mn; }
    } else if (w >= 16 && w < 16 + RPC) {
        const int t = w - 16;
        float v0 = s_h[t][s_idxt[lane]];
        float v1 = s_h[t][s_idxt[lane + 32]];
        float mx = fmaxf(v0, v1), mn = fminf(v0, v1);
        #pragma unroll
        for (int o = 16; o; o >>= 1) {
            mx = fmaxf(mx, __shfl_xor_sync(0xffffffffu, mx, o));
            mn = fminf(mn, __shfl_xor_sync(0xffffffffu, mn, o));
        }
        if (lane == 0) { s_amax[t] = mx; s_amin[t] = mn; }
    }
    __syncthreads();

    if (tid < RPC*F) {
        const int t = tid >> 6;
        const float c   = s_o[t][tid & 63];
        const float wmax = s_wmm[0], wmin = s_wmm[1];
        const float amx = s_amax[t], amn = s_amin[t];
        float m = fmaxf(fmaxf(amx*wmax*c, amx*wmin*c),
                        fmaxf(amn*wmax*c, amn*wmin*c));
        s_U[tid] = fast_tanh(m);
    }
    __syncthreads();

    {
        const float4* __restrict__ ms4 = (const float4*)s_U;
        #pragma unroll
        for (int k = 0; k < 2; ++k) {
            const int m = w*2 + k;
            const float4* __restrict__ key4 =
                (const float4*)(mem_keys + m*TF + r*(RPC*F));
            float p0 = 0.f, p1 = 0.f, p2 = 0.f, p3 = 0.f;
            #pragma unroll
            for (int c = 0; c < 4; ++c) {
                float4 kk = key4[c*32 + lane];
                float4 mm = ms4[c*32 + lane];
                p0 = fmaf(kk.x, mm.x, p0);
                p1 = fmaf(kk.y, mm.y, p1);
                p2 = fmaf(kk.z, mm.z, p2);
                p3 = fmaf(kk.w, mm.w, p3);
            }
            float acc = (p0 + p1) + (p2 + p3);
            #pragma unroll
            for (int o = 16; o; o >>= 1)
                acc += __shfl_xor_sync(0xffffffffu, acc, o);
            if (lane < CPB)
                stc_f32(smem_u32(&s_lp[r][m]), lane, acc);
        }
    }
    cluster_arrive();
    float rv[4];
    {
        const int f = tid & 63, q = tid >> 6;
        #pragma unroll
        for (int k = 0; k < 4; ++k)
            rv[k] = __ldg(mem_vals + (q*4 + k)*F + f);
    }
    cluster_wait();

    if (w == 0) {
        float l0 = 0.f, l1 = 0.f;
        #pragma unroll
        for (int rr = 0; rr < CPB; ++rr) {
            l0 += s_lp[rr][lane];
            l1 += s_lp[rr][lane + 32];
        }
        float mx = fmaxf(l0, l1);
        #pragma unroll
        for (int o = 16; o; o >>= 1)
            mx = fmaxf(mx, __shfl_xor_sync(0xffffffffu, mx, o));
        float e0 = __expf(l0 - mx), e1 = __expf(l1 - mx);
        float s = e0 + e1;
        #pragma unroll
        for (int o = 16; o; o >>= 1)
            s += __shfl_xor_sync(0xffffffffu, s, o);
        float inv = 1.0f / s;
        s_attn[lane]      = e0 * inv;
        s_attn[lane + 32] = e1 * inv;
        if (lane == 0) s_imp = inv;
    }
    __syncthreads();

    {
        const int f = tid & 63, q = tid >> 6;
        float acc = 0.f;
        #pragma unroll
        for (int k = 0; k < 4; ++k)
            acc = fmaf(s_attn[q*4 + k], rv[k], acc);
        s_U[2048 + q*64 + f] = acc;
    }
    __syncthreads();

    if (w < RPC) {
        float tg0 = 0.f, tg1 = 0.f;
        #pragma unroll
        for (int q = 0; q < 16; ++q) {
            tg0 += s_U[2048 + q*64 + lane];
            tg1 += s_U[2048 + q*64 + lane + 32];
        }
        float d0 = s_in[w][lane]      - tg0;
        float d1 = s_in[w][lane + 32] - tg1;
        float a2 = d0*d0 + d1*d1;
        #pragma unroll
        for (int o = 16; o; o >>= 1)
            a2 += __shfl_xor_sync(0xffffffffu, a2, o);
        if (lane == 0) {
            float nrm = sqrtf(a2);
            float hs  = fminf(fmaxf(0.2f*nrm + 0.5f, 0.f), 1.f);
            d_out[b*T + r*RPC + w]       = 0.5f - hs;
            d_out[B*T + b*T + r*RPC + w] = s_imp;
        }
    }
}

// =====================================================================
extern "C" void kernel_launch(void* const* d_in, const int* in_sizes, int n_in,
                              void* d_out, int out_size) {
    const float* inp      = (const float*)d_in[0];
    const float* Wk       = (const float*)d_in[1];
    const float* bk       = (const float*)d_in[2];
    const float* Wv       = (const float*)d_in[3];
    const float* bv       = (const float*)d_in[4];
    const float* w_s      = (const float*)d_in[5];
    const float* mem_keys = (const float*)d_in[6];
    const float* mem_vals = (const float*)d_in[7];
    float* out = (float*)d_out;

    cudaLaunchAttribute attr[1];
    attr[0].id = cudaLaunchAttributeClusterDimension;

    cudaFuncSetAttribute(fused16,
                         cudaFuncAttributeNonPortableClusterSizeAllowed, 1);
    cudaLaunchConfig_t probe = {};
    probe.gridDim  = dim3(B*16, 1, 1);
    probe.blockDim = dim3(NTH, 1, 1);
    int maxC = 0;
    cudaError_t pe = cudaOccupancyMaxPotentialClusterSize(&maxC, fused16, &probe);
    (void)cudaGetLastError();

    cudaLaunchConfig_t cfg = {};
    cfg.blockDim = dim3(NTH, 1, 1);
    cfg.attrs = attr;
    cfg.numAttrs = 1;

    if (pe == cudaSuccess && maxC >= 16) {
        cfg.gridDim = dim3(B*16, 1, 1);
        attr[0].val.clusterDim = {16, 1, 1};
        cudaLaunchKernelEx(&cfg, fused16,
                           inp, Wk, bk, Wv, bv, w_s, mem_keys, mem_vals, out);
    } else {
        cfg.gridDim = dim3(B*8, 1, 1);
        attr[0].val.clusterDim = {8, 1, 1};
        cudaLaunchKernelEx(&cfg, fused8,
                           inp, Wk, bk, Wv, bv, w_s, mem_keys, mem_vals, out);
    }
}